// round 5
// baseline (speedup 1.0000x reference)
#include <cuda_runtime.h>
#include <math.h>
#include <stdint.h>

#define NN  128000   // B*NPG nodes
#define EE  2048000  // B*EPG edges
#define BBG 128      // graphs
#define NPG 1000
#define EPG 16000
#define DD  128
#define KK  64

// ---------------- scratch (static device globals; no allocs) ----------------
__device__ int   g_deg[NN];
__device__ float g_dinv[NN];
__device__ int   g_rowptr[NN];      // absolute start into g_csr_src
__device__ int   g_csr_src[EE];     // graph-LOCAL src index per (dst-sorted) edge
__device__ float g_bufA[(size_t)NN * DD];
__device__ float g_bufB[(size_t)NN * DD];
__device__ float g_pool[BBG * DD];

// ---------------- f32x2 helpers ----------------
__device__ __forceinline__ void fma2(unsigned long long& d, unsigned long long a,
                                     unsigned long long b) {
    asm("fma.rn.f32x2 %0, %1, %2, %0;" : "+l"(d) : "l"(a), "l"(b));
}
__device__ __forceinline__ unsigned long long pack2(float x) {
    unsigned long long r;
    unsigned u = __float_as_uint(x);
    asm("mov.b64 %0, {%1, %1};" : "=l"(r) : "r"(u));
    return r;
}
__device__ __forceinline__ float2 unpack2(unsigned long long v) {
    unsigned lo, hi;
    asm("mov.b64 {%0, %1}, %2;" : "=r"(lo), "=r"(hi) : "l"(v));
    return make_float2(__uint_as_float(lo), __uint_as_float(hi));
}

// ---------------- fused CSR build: one CTA per graph (proven) ----------------
__global__ __launch_bounds__(1024) void k_build(const int* __restrict__ src,
                                                const int* __restrict__ dst) {
    __shared__ int cnt[NPG];
    __shared__ int ws[32];
    int b = blockIdx.x;
    int t = threadIdx.x;
    int ebase = b * EPG;
    int nbase = b * NPG;

    if (t < NPG) cnt[t] = 0;
    __syncthreads();

    for (int e = t; e < EPG; e += 1024)
        atomicAdd(&cnt[dst[ebase + e] - nbase], 1);
    __syncthreads();

    int val = (t < NPG) ? cnt[t] : 0;
    int x = val;
    unsigned m = 0xffffffffu;
    #pragma unroll
    for (int o = 1; o < 32; o <<= 1) {
        int y = __shfl_up_sync(m, x, o);
        if ((t & 31) >= o) x += y;
    }
    if ((t & 31) == 31) ws[t >> 5] = x;
    __syncthreads();
    if (t < 32) {
        int y = ws[t];
        int z = y;
        #pragma unroll
        for (int o = 1; o < 32; o <<= 1) {
            int w = __shfl_up_sync(m, z, o);
            if (t >= o) z += w;
        }
        ws[t] = z - y;
    }
    __syncthreads();
    int excl = x + ws[t >> 5] - val;
    __syncthreads();

    if (t < NPG) {
        int v = nbase + t;
        g_deg[v]    = val;
        g_rowptr[v] = ebase + excl;
        g_dinv[v]   = rsqrtf((float)(val + 1));  // +1 self-loop
        cnt[t] = excl;
    }
    __syncthreads();

    for (int e = t; e < EPG; e += 1024) {
        int s = src[ebase + e] - nbase;
        int d = dst[ebase + e] - nbase;
        int p = atomicAdd(&cnt[d], 1);
        g_csr_src[ebase + p] = s;
    }
}

// ---------------- GEMM v3 (f32x2, 8x8 per-thread, conflict-free LDS) ----------
// O[r,:] = dinv[r] * (X[r,:] @ W).  128-row tile, 256 threads, grid 1000.
// Warp (8 total): wr = w>>2 (row half), wc = w&3 (32-col group).
// Lane: lr = lane>>2 (0..7), lc = lane&3 (0..3).
// Thread rows: wr*64 + lr + 8i (i=0..7, stride-8 interleave -> bank 4*lr,
//   conflict-free float4 k-quad reads). Thread cols: wc*32 + lc*8 (8 cols,
//   two natural ulonglong2 W pairs, 8-way broadcast).
#define XPAD 132

__global__ __launch_bounds__(256) void k_gemm(const float* __restrict__ X,
                                              const float* __restrict__ W,
                                              float* __restrict__ O) {
    extern __shared__ float sm[];
    float* sW = sm;                 // 128*128
    float* sX = sm + DD * DD;       // 128*132
    int t = threadIdx.x;
    size_t row0 = (size_t)blockIdx.x * 128;

    // load W (plain row-major)
    const float4* W4 = (const float4*)W;
    float4* sW4 = (float4*)sW;
    #pragma unroll
    for (int i = 0; i < 16; i++) sW4[i * 256 + t] = W4[i * 256 + t];

    // load X tile, rows padded to 132 floats
    const float4* X4 = (const float4*)(X + row0 * DD);
    #pragma unroll
    for (int i = 0; i < 16; i++) {
        int gid = i * 256 + t;           // 4096 float4s: 128 rows x 32 groups
        int r = gid >> 5, c4 = gid & 31;
        *(float4*)&sX[r * XPAD + c4 * 4] = X4[gid];
    }
    __syncthreads();

    int w = t >> 5, lane = t & 31;
    int wr = w >> 2, wc = w & 3;
    int lr = lane >> 2, lc = lane & 3;
    int rbase = wr * 64 + lr;            // + 8i
    int c0 = wc * 32 + lc * 8;
    int widx = wc * 8 + lc * 2;          // ulonglong2 index within a W k-row

    unsigned long long acc[8][4];
    #pragma unroll
    for (int i = 0; i < 8; i++)
        #pragma unroll
        for (int j = 0; j < 4; j++) acc[i][j] = 0ull;

    const ulonglong2* sWp = (const ulonglong2*)sW;  // 32 ull2 per k-row
    const float* xrow = sX + rbase * XPAD;

    #pragma unroll 2
    for (int k0 = 0; k0 < DD; k0 += 4) {
        float4 xv[8];
        #pragma unroll
        for (int i = 0; i < 8; i++)
            xv[i] = *(const float4*)&xrow[i * 8 * XPAD + k0];
        #pragma unroll
        for (int kk = 0; kk < 4; kk++) {
            ulonglong2 wa = sWp[(k0 + kk) * 32 + widx];
            ulonglong2 wb = sWp[(k0 + kk) * 32 + widx + 1];
            #pragma unroll
            for (int i = 0; i < 8; i++) {
                float xs = (kk == 0) ? xv[i].x : (kk == 1) ? xv[i].y
                         : (kk == 2) ? xv[i].z : xv[i].w;
                unsigned long long ad = pack2(xs);
                fma2(acc[i][0], ad, wa.x);
                fma2(acc[i][1], ad, wa.y);
                fma2(acc[i][2], ad, wb.x);
                fma2(acc[i][3], ad, wb.y);
            }
        }
    }

    #pragma unroll
    for (int i = 0; i < 8; i++) {
        size_t row = row0 + rbase + 8 * i;
        float dv = g_dinv[row];
        float2 p0 = unpack2(acc[i][0]);
        float2 p1 = unpack2(acc[i][1]);
        float2 p2 = unpack2(acc[i][2]);
        float2 p3 = unpack2(acc[i][3]);
        float4 o0 = make_float4(dv * p0.x, dv * p0.y, dv * p1.x, dv * p1.y);
        float4 o1 = make_float4(dv * p2.x, dv * p2.y, dv * p3.x, dv * p3.y);
        *(float4*)&O[row * DD + c0] = o0;
        *(float4*)&O[row * DD + c0 + 4] = o1;
    }
}

// ---------------- aggregation (L2 gather; proven) ----------------
// OUT[v,:] = relu(dinv[v] * (sum_{s in in(v)} XW'[s,:] + XW'[v,:]) + bias)
// where XW' rows are pre-scaled by dinv[src] in the GEMM epilogue.
__global__ __launch_bounds__(256) void k_agg(const float* __restrict__ XW,
                                             float* __restrict__ OUT,
                                             const float* __restrict__ bias) {
    int warp = (blockIdx.x * blockDim.x + threadIdx.x) >> 5;
    int lane = threadIdx.x & 31;
    if (warp >= NN) return;
    int v = warp;
    int nbase = (v / NPG) * NPG;

    const float4* X4 = (const float4*)XW;
    float4 acc = X4[(size_t)v * 32 + lane];   // self-loop term

    int start = g_rowptr[v];
    int cnt = g_deg[v];
    for (int base = 0; base < cnt; base += 32) {
        int idx = base + lane;
        int s = (idx < cnt) ? g_csr_src[start + idx] : 0;
        int mcnt = min(32, cnt - base);
        int j = 0;
        for (; j + 4 <= mcnt; j += 4) {
            #pragma unroll
            for (int u = 0; u < 4; u++) {
                int sj = __shfl_sync(0xffffffffu, s, j + u);
                float4 xs = X4[(size_t)(nbase + sj) * 32 + lane];
                acc.x += xs.x; acc.y += xs.y; acc.z += xs.z; acc.w += xs.w;
            }
        }
        for (; j < mcnt; j++) {
            int sj = __shfl_sync(0xffffffffu, s, j);
            float4 xs = X4[(size_t)(nbase + sj) * 32 + lane];
            acc.x += xs.x; acc.y += xs.y; acc.z += xs.z; acc.w += xs.w;
        }
    }

    float dv = g_dinv[v];
    float4 bb = ((const float4*)bias)[lane];
    float4 res = make_float4(fmaxf(dv * acc.x + bb.x, 0.f),
                             fmaxf(dv * acc.y + bb.y, 0.f),
                             fmaxf(dv * acc.z + bb.z, 0.f),
                             fmaxf(dv * acc.w + bb.w, 0.f));
    ((float4*)OUT)[(size_t)v * 32 + lane] = res;
}

// ---------------- per-graph mean pool / K ----------------
__global__ void k_pool(const float* __restrict__ NE) {
    int b = blockIdx.x;
    int t = threadIdx.x;
    int dd = t & 127;
    int q = t >> 7;
    const float* base = NE + (size_t)b * NPG * DD + dd;
    float s = 0.f;
    int r0 = q * (NPG / 4);
    #pragma unroll 4
    for (int r = 0; r < NPG / 4; r++) s += base[(size_t)(r0 + r) * DD];
    __shared__ float sm[512];
    sm[t] = s;
    __syncthreads();
    if (q == 0) {
        float tot = sm[dd] + sm[dd + 128] + sm[dd + 256] + sm[dd + 384];
        g_pool[b * DD + dd] = tot * (1.0f / KK);
    }
}

// ---------------- final MLP ----------------
__global__ void k_mlp(const float* __restrict__ W1, const float* __restrict__ b1,
                      const float* __restrict__ W2, const float* __restrict__ b2,
                      float* __restrict__ out) {
    int b = blockIdx.x;
    int t = threadIdx.x;
    __shared__ float p[128], h[128];
    p[t] = g_pool[b * 128 + t];
    __syncthreads();
    float acc = b1[t];
    #pragma unroll 4
    for (int d = 0; d < 128; d++) acc += p[d] * W1[d * 128 + t];
    h[t] = fmaxf(acc, 0.f);
    __syncthreads();
    if (t < 10) {
        float o = b2[t];
        #pragma unroll 4
        for (int j = 0; j < 128; j++) o += h[j] * W2[j * 10 + t];
        out[b * 10 + t] = o;
    }
}

// ---------------- launch ----------------
extern "C" void kernel_launch(void* const* d_in, const int* in_sizes, int n_in,
                              void* d_out, int out_size) {
    const float* x     = (const float*)d_in[0];
    const int*   ei    = (const int*)d_in[1];
    const float* W_pre = (const float*)d_in[3];
    const float* b_pre = (const float*)d_in[4];
    const float* W_emb = (const float*)d_in[5];
    const float* b_emb = (const float*)d_in[6];
    // d_in[2] batch, d_in[7] W_asn, d_in[8] b_asn dead (softmax rows sum to 1)
    const float* W1 = (const float*)d_in[9];
    const float* b1 = (const float*)d_in[10];
    const float* W2 = (const float*)d_in[11];
    const float* b2 = (const float*)d_in[12];
    float* out = (float*)d_out;

    int E = in_sizes[1] / 2;
    int N = in_sizes[0] / DD;
    const int* src = ei;
    const int* dst = ei + E;

    void *pA, *pB;
    cudaGetSymbolAddress(&pA, g_bufA);
    cudaGetSymbolAddress(&pB, g_bufB);
    float* bufA = (float*)pA;
    float* bufB = (float*)pB;

    const int smem_gemm = (DD * DD + DD * XPAD) * (int)sizeof(float);  // 133120B
    cudaFuncSetAttribute(k_gemm, cudaFuncAttributeMaxDynamicSharedMemorySize, smem_gemm);

    // normalized-adjacency CSR build (per-graph, smem histogram + scan + fill)
    k_build<<<BBG, 1024>>>(src, dst);

    // conv1: h = relu(Ahat @ (x @ W_pre) + b_pre)   [dinv folded into GEMM rows]
    k_gemm<<<N / 128, 256, smem_gemm>>>(x, W_pre, bufA);
    k_agg<<<N / 8, 256>>>(bufA, bufB, b_pre);

    // conv2: NE = relu(Ahat @ (h @ W_emb) + b_emb)
    k_gemm<<<N / 128, 256, smem_gemm>>>(bufB, W_emb, bufA);
    k_agg<<<N / 8, 256>>>(bufA, bufB, b_emb);

    // pool (assignment branch collapses to mean/K) + MLP head
    k_pool<<<BBG, 512>>>(bufB);
    k_mlp<<<BBG, 128>>>(W1, b1, W2, b2, out);
}

// round 6
// speedup vs baseline: 1.0645x; 1.0645x over previous
#include <cuda_runtime.h>
#include <math.h>
#include <stdint.h>

#define NN  128000   // B*NPG nodes
#define EE  2048000  // B*EPG edges
#define BBG 128      // graphs
#define NPG 1000
#define EPG 16000
#define DD  128
#define KK  64

// ---------------- scratch (static device globals; no allocs) ----------------
__device__ int   g_deg[NN];
__device__ float g_dinv[NN];
__device__ int   g_rowptr[NN];      // absolute start into g_csr_src
__device__ int   g_csr_src[EE];     // graph-LOCAL src index per (dst-sorted) edge
__device__ float g_bufA[(size_t)NN * DD];
__device__ float g_bufB[(size_t)NN * DD];
__device__ float g_pool[BBG * DD];

// ---------------- f32x2 helpers ----------------
__device__ __forceinline__ void fma2(unsigned long long& d, unsigned long long a,
                                     unsigned long long b) {
    asm("fma.rn.f32x2 %0, %1, %2, %0;" : "+l"(d) : "l"(a), "l"(b));
}
__device__ __forceinline__ unsigned long long pack2(float x) {
    unsigned long long r;
    unsigned u = __float_as_uint(x);
    asm("mov.b64 %0, {%1, %1};" : "=l"(r) : "r"(u));
    return r;
}
__device__ __forceinline__ float2 unpack2(unsigned long long v) {
    unsigned lo, hi;
    asm("mov.b64 {%0, %1}, %2;" : "=r"(lo), "=r"(hi) : "l"(v));
    return make_float2(__uint_as_float(lo), __uint_as_float(hi));
}

// ---------------- fused CSR build: one CTA per graph (proven) ----------------
__global__ __launch_bounds__(1024) void k_build(const int* __restrict__ src,
                                                const int* __restrict__ dst) {
    __shared__ int cnt[NPG];
    __shared__ int ws[32];
    int b = blockIdx.x;
    int t = threadIdx.x;
    int ebase = b * EPG;
    int nbase = b * NPG;

    if (t < NPG) cnt[t] = 0;
    __syncthreads();

    for (int e = t; e < EPG; e += 1024)
        atomicAdd(&cnt[dst[ebase + e] - nbase], 1);
    __syncthreads();

    int val = (t < NPG) ? cnt[t] : 0;
    int x = val;
    unsigned m = 0xffffffffu;
    #pragma unroll
    for (int o = 1; o < 32; o <<= 1) {
        int y = __shfl_up_sync(m, x, o);
        if ((t & 31) >= o) x += y;
    }
    if ((t & 31) == 31) ws[t >> 5] = x;
    __syncthreads();
    if (t < 32) {
        int y = ws[t];
        int z = y;
        #pragma unroll
        for (int o = 1; o < 32; o <<= 1) {
            int w = __shfl_up_sync(m, z, o);
            if (t >= o) z += w;
        }
        ws[t] = z - y;
    }
    __syncthreads();
    int excl = x + ws[t >> 5] - val;
    __syncthreads();

    if (t < NPG) {
        int v = nbase + t;
        g_deg[v]    = val;
        g_rowptr[v] = ebase + excl;
        g_dinv[v]   = rsqrtf((float)(val + 1));  // +1 self-loop
        cnt[t] = excl;
    }
    __syncthreads();

    for (int e = t; e < EPG; e += 1024) {
        int s = src[ebase + e] - nbase;
        int d = dst[ebase + e] - nbase;
        int p = atomicAdd(&cnt[d], 1);
        g_csr_src[ebase + p] = s;
    }
}

// ---------------- GEMM v4 (f32x2, conflict-free LDS, 2 CTAs/SM) ---------------
// O[r,:] = dinv[r] * (X[r,:] @ W).  64-row tile, 256 threads, grid 2000.
// smem: sW [128][128] (64KB) + sX [64][132] (33KB) = 99328B -> 2 CTAs/SM.
// Warp (8): wr = w>>2 (0..1 row half), wc = w&3 (32-col group).
// Lane: lr = lane>>2 (0..7), lc = lane&3.
// Thread rows: wr*32 + lr + 8i (i=0..3) -> lane bank offset 4*lr, float4
// k-quad reads conflict-free. Cols: wc*32 + lc*8 (two natural ull2 W pairs,
// 8-way broadcast).
#define XPAD 132

__global__ __launch_bounds__(256, 2) void k_gemm(const float* __restrict__ X,
                                                 const float* __restrict__ W,
                                                 float* __restrict__ O) {
    extern __shared__ float sm[];
    float* sW = sm;                 // 128*128
    float* sX = sm + DD * DD;       // 64*132
    int t = threadIdx.x;
    size_t row0 = (size_t)blockIdx.x * 64;

    // load W (plain row-major)
    const float4* W4 = (const float4*)W;
    float4* sW4 = (float4*)sW;
    #pragma unroll
    for (int i = 0; i < 16; i++) sW4[i * 256 + t] = W4[i * 256 + t];

    // load X tile (64 rows), rows padded to 132 floats
    const float4* X4 = (const float4*)(X + row0 * DD);
    #pragma unroll
    for (int i = 0; i < 8; i++) {
        int gid = i * 256 + t;           // 2048 float4s: 64 rows x 32 groups
        int r = gid >> 5, c4 = gid & 31;
        *(float4*)&sX[r * XPAD + c4 * 4] = X4[gid];
    }
    __syncthreads();

    int w = t >> 5, lane = t & 31;
    int wr = w >> 2, wc = w & 3;
    int lr = lane >> 2, lc = lane & 3;
    int rbase = wr * 32 + lr;            // + 8i, i=0..3
    int c0 = wc * 32 + lc * 8;
    int widx = wc * 8 + lc * 2;          // ulonglong2 index within a W k-row

    unsigned long long acc[4][4];
    #pragma unroll
    for (int i = 0; i < 4; i++)
        #pragma unroll
        for (int j = 0; j < 4; j++) acc[i][j] = 0ull;

    const ulonglong2* sWp = (const ulonglong2*)sW;  // 32 ull2 per k-row
    const float* xrow = sX + rbase * XPAD;

    #pragma unroll 2
    for (int k0 = 0; k0 < DD; k0 += 4) {
        float4 xv[4];
        #pragma unroll
        for (int i = 0; i < 4; i++)
            xv[i] = *(const float4*)&xrow[i * 8 * XPAD + k0];
        #pragma unroll
        for (int kk = 0; kk < 4; kk++) {
            ulonglong2 wa = sWp[(k0 + kk) * 32 + widx];
            ulonglong2 wb = sWp[(k0 + kk) * 32 + widx + 1];
            #pragma unroll
            for (int i = 0; i < 4; i++) {
                float xs = (kk == 0) ? xv[i].x : (kk == 1) ? xv[i].y
                         : (kk == 2) ? xv[i].z : xv[i].w;
                unsigned long long ad = pack2(xs);
                fma2(acc[i][0], ad, wa.x);
                fma2(acc[i][1], ad, wa.y);
                fma2(acc[i][2], ad, wb.x);
                fma2(acc[i][3], ad, wb.y);
            }
        }
    }

    #pragma unroll
    for (int i = 0; i < 4; i++) {
        size_t row = row0 + rbase + 8 * i;
        float dv = g_dinv[row];
        float2 p0 = unpack2(acc[i][0]);
        float2 p1 = unpack2(acc[i][1]);
        float2 p2 = unpack2(acc[i][2]);
        float2 p3 = unpack2(acc[i][3]);
        float4 o0 = make_float4(dv * p0.x, dv * p0.y, dv * p1.x, dv * p1.y);
        float4 o1 = make_float4(dv * p2.x, dv * p2.y, dv * p3.x, dv * p3.y);
        *(float4*)&O[row * DD + c0] = o0;
        *(float4*)&O[row * DD + c0 + 4] = o1;
    }
}

// ---------------- aggregation (L2 gather; proven) ----------------
// OUT[v,:] = relu(dinv[v] * (sum_{s in in(v)} XW'[s,:] + XW'[v,:]) + bias)
// where XW' rows are pre-scaled by dinv[src] in the GEMM epilogue.
__global__ __launch_bounds__(256) void k_agg(const float* __restrict__ XW,
                                             float* __restrict__ OUT,
                                             const float* __restrict__ bias) {
    int warp = (blockIdx.x * blockDim.x + threadIdx.x) >> 5;
    int lane = threadIdx.x & 31;
    if (warp >= NN) return;
    int v = warp;
    int nbase = (v / NPG) * NPG;

    const float4* X4 = (const float4*)XW;
    float4 acc = X4[(size_t)v * 32 + lane];   // self-loop term

    int start = g_rowptr[v];
    int cnt = g_deg[v];
    for (int base = 0; base < cnt; base += 32) {
        int idx = base + lane;
        int s = (idx < cnt) ? g_csr_src[start + idx] : 0;
        int mcnt = min(32, cnt - base);
        int j = 0;
        for (; j + 4 <= mcnt; j += 4) {
            #pragma unroll
            for (int u = 0; u < 4; u++) {
                int sj = __shfl_sync(0xffffffffu, s, j + u);
                float4 xs = X4[(size_t)(nbase + sj) * 32 + lane];
                acc.x += xs.x; acc.y += xs.y; acc.z += xs.z; acc.w += xs.w;
            }
        }
        for (; j < mcnt; j++) {
            int sj = __shfl_sync(0xffffffffu, s, j);
            float4 xs = X4[(size_t)(nbase + sj) * 32 + lane];
            acc.x += xs.x; acc.y += xs.y; acc.z += xs.z; acc.w += xs.w;
        }
    }

    float dv = g_dinv[v];
    float4 bb = ((const float4*)bias)[lane];
    float4 res = make_float4(fmaxf(dv * acc.x + bb.x, 0.f),
                             fmaxf(dv * acc.y + bb.y, 0.f),
                             fmaxf(dv * acc.z + bb.z, 0.f),
                             fmaxf(dv * acc.w + bb.w, 0.f));
    ((float4*)OUT)[(size_t)v * 32 + lane] = res;
}

// ---------------- per-graph mean pool / K ----------------
__global__ void k_pool(const float* __restrict__ NE) {
    int b = blockIdx.x;
    int t = threadIdx.x;
    int dd = t & 127;
    int q = t >> 7;
    const float* base = NE + (size_t)b * NPG * DD + dd;
    float s = 0.f;
    int r0 = q * (NPG / 4);
    #pragma unroll 4
    for (int r = 0; r < NPG / 4; r++) s += base[(size_t)(r0 + r) * DD];
    __shared__ float sm[512];
    sm[t] = s;
    __syncthreads();
    if (q == 0) {
        float tot = sm[dd] + sm[dd + 128] + sm[dd + 256] + sm[dd + 384];
        g_pool[b * DD + dd] = tot * (1.0f / KK);
    }
}

// ---------------- final MLP ----------------
__global__ void k_mlp(const float* __restrict__ W1, const float* __restrict__ b1,
                      const float* __restrict__ W2, const float* __restrict__ b2,
                      float* __restrict__ out) {
    int b = blockIdx.x;
    int t = threadIdx.x;
    __shared__ float p[128], h[128];
    p[t] = g_pool[b * 128 + t];
    __syncthreads();
    float acc = b1[t];
    #pragma unroll 4
    for (int d = 0; d < 128; d++) acc += p[d] * W1[d * 128 + t];
    h[t] = fmaxf(acc, 0.f);
    __syncthreads();
    if (t < 10) {
        float o = b2[t];
        #pragma unroll 4
        for (int j = 0; j < 128; j++) o += h[j] * W2[j * 10 + t];
        out[b * 10 + t] = o;
    }
}

// ---------------- launch ----------------
extern "C" void kernel_launch(void* const* d_in, const int* in_sizes, int n_in,
                              void* d_out, int out_size) {
    const float* x     = (const float*)d_in[0];
    const int*   ei    = (const int*)d_in[1];
    const float* W_pre = (const float*)d_in[3];
    const float* b_pre = (const float*)d_in[4];
    const float* W_emb = (const float*)d_in[5];
    const float* b_emb = (const float*)d_in[6];
    // d_in[2] batch, d_in[7] W_asn, d_in[8] b_asn dead (softmax rows sum to 1)
    const float* W1 = (const float*)d_in[9];
    const float* b1 = (const float*)d_in[10];
    const float* W2 = (const float*)d_in[11];
    const float* b2 = (const float*)d_in[12];
    float* out = (float*)d_out;

    int E = in_sizes[1] / 2;
    int N = in_sizes[0] / DD;
    const int* src = ei;
    const int* dst = ei + E;

    void *pA, *pB;
    cudaGetSymbolAddress(&pA, g_bufA);
    cudaGetSymbolAddress(&pB, g_bufB);
    float* bufA = (float*)pA;
    float* bufB = (float*)pB;

    const int smem_gemm = (DD * DD + 64 * XPAD) * (int)sizeof(float);  // 99328B
    cudaFuncSetAttribute(k_gemm, cudaFuncAttributeMaxDynamicSharedMemorySize, smem_gemm);

    // normalized-adjacency CSR build (per-graph, smem histogram + scan + fill)
    k_build<<<BBG, 1024>>>(src, dst);

    // conv1: h = relu(Ahat @ (x @ W_pre) + b_pre)   [dinv folded into GEMM rows]
    k_gemm<<<N / 64, 256, smem_gemm>>>(x, W_pre, bufA);
    k_agg<<<N / 8, 256>>>(bufA, bufB, b_pre);

    // conv2: NE = relu(Ahat @ (h @ W_emb) + b_emb)
    k_gemm<<<N / 64, 256, smem_gemm>>>(bufB, W_emb, bufA);
    k_agg<<<N / 8, 256>>>(bufA, bufB, b_emb);

    // pool (assignment branch collapses to mean/K) + MLP head
    k_pool<<<BBG, 512>>>(bufB);
    k_mlp<<<BBG, 128>>>(W1, b1, W2, b2, out);
}